// round 1
// baseline (speedup 1.0000x reference)
#include <cuda_runtime.h>

#define NMAX 50000
#define FEAT 64
#define OUTF 16

// Scratch (no allocations allowed)
__device__ float g_h1[NMAX * FEAT];     // X@W1 * norm_src, then reused as layer-1 output
__device__ float g_agg1[NMAX * FEAT];   // scatter accumulator layer 1
__device__ float g_h2[NMAX * OUTF];     // out1@W2 * norm_src
__device__ float g_norm_src[NMAX];
__device__ float g_norm_dst[NMAX];
__device__ int   g_deg_src[NMAX];
__device__ int   g_deg_dst[NMAX];

// ---------------- degree / norm ----------------
__global__ void zero_deg_kernel(int n) {
    int i = blockIdx.x * blockDim.x + threadIdx.x;
    if (i < n) { g_deg_src[i] = 0; g_deg_dst[i] = 0; }
}

__global__ void count_deg_kernel(const int* __restrict__ src,
                                 const int* __restrict__ dst, int e) {
    int i = blockIdx.x * blockDim.x + threadIdx.x;
    if (i < e) {
        atomicAdd(&g_deg_src[src[i]], 1);
        atomicAdd(&g_deg_dst[dst[i]], 1);
    }
}

__global__ void norm_kernel(int n) {
    int i = blockIdx.x * blockDim.x + threadIdx.x;
    if (i < n) {
        g_norm_src[i] = rsqrtf(fmaxf((float)g_deg_src[i], 1.0f));
        g_norm_dst[i] = rsqrtf(fmaxf((float)g_deg_dst[i], 1.0f));
    }
}

// ---------------- GEMM 1: h1 = (X @ W1) * norm_src ----------------
// One warp per row; thread computes cols lane and lane+32. W1 (64x64) in smem.
__global__ void gemm1_kernel(const float* __restrict__ x,
                             const float* __restrict__ w1, int n) {
    __shared__ float ws[FEAT * FEAT];
    int tid = threadIdx.x;
    for (int i = tid; i < FEAT * FEAT; i += blockDim.x) ws[i] = w1[i];
    __syncthreads();

    int warp = tid >> 5;
    int lane = tid & 31;
    int row = blockIdx.x * (blockDim.x >> 5) + warp;
    if (row >= n) return;

    const float* xr = x + row * FEAT;
    float acc0 = 0.f, acc1 = 0.f;
#pragma unroll
    for (int k = 0; k < FEAT; k++) {
        float xv = __ldg(&xr[k]);
        acc0 = fmaf(xv, ws[k * FEAT + lane], acc0);
        acc1 = fmaf(xv, ws[k * FEAT + lane + 32], acc1);
    }
    float s = g_norm_src[row];
    g_h1[row * FEAT + lane]      = acc0 * s;
    g_h1[row * FEAT + lane + 32] = acc1 * s;
}

// ---------------- zero float buffer ----------------
__global__ void zero_f_kernel(float* __restrict__ p, int count) {
    int i = blockIdx.x * blockDim.x + threadIdx.x;
    if (i < count) p[i] = 0.0f;
}

// ---------------- scatter layer 1: agg1[dst] += h1[src] (64 f/edge) ----------------
__global__ void scatter64_kernel(const int* __restrict__ src,
                                 const int* __restrict__ dst, int e) {
    int i = blockIdx.x * blockDim.x + threadIdx.x;
    int total = e * FEAT;
    if (i >= total) return;
    int edge = i >> 6;
    int f = i & 63;
    int s = __ldg(&src[edge]);
    int d = __ldg(&dst[edge]);
    atomicAdd(&g_agg1[d * FEAT + f], g_h1[s * FEAT + f]);
}

// ---------------- finalize 1: out1 = relu(agg1 * norm_dst + b1) -> g_h1 ----------------
__global__ void finalize1_kernel(const float* __restrict__ b1, int n) {
    int i = blockIdx.x * blockDim.x + threadIdx.x;
    int total = n * FEAT;
    if (i >= total) return;
    int r = i >> 6;
    int c = i & 63;
    float v = g_agg1[i] * g_norm_dst[r] + __ldg(&b1[c]);
    g_h1[i] = fmaxf(v, 0.0f);
}

// ---------------- GEMM 2: h2 = (out1 @ W2) * norm_src ----------------
// 16 threads per row (one per out col), 2 rows per warp. W2 (64x16) in smem.
__global__ void gemm2_kernel(const float* __restrict__ w2, int n) {
    __shared__ float ws[FEAT * OUTF];
    int tid = threadIdx.x;
    for (int i = tid; i < FEAT * OUTF; i += blockDim.x) ws[i] = w2[i];
    __syncthreads();

    int group = tid >> 4;               // 16 groups per 256-thread block
    int col = tid & 15;
    int row = blockIdx.x * (blockDim.x >> 4) + group;
    if (row >= n) return;

    const float* hr = g_h1 + row * FEAT;
    float acc = 0.f;
#pragma unroll
    for (int k = 0; k < FEAT; k++) {
        acc = fmaf(hr[k], ws[k * OUTF + col], acc);
    }
    g_h2[row * OUTF + col] = acc * g_norm_src[row];
}

// ---------------- scatter layer 2: out[dst] += h2[src] (16 f/edge) ----------------
__global__ void scatter16_kernel(const int* __restrict__ src,
                                 const int* __restrict__ dst,
                                 float* __restrict__ out, int e) {
    int i = blockIdx.x * blockDim.x + threadIdx.x;
    int total = e * OUTF;
    if (i >= total) return;
    int edge = i >> 4;
    int f = i & 15;
    int s = __ldg(&src[edge]);
    int d = __ldg(&dst[edge]);
    atomicAdd(&out[d * OUTF + f], g_h2[s * OUTF + f]);
}

// ---------------- finalize 2: out = out * norm_dst + b2 (in place) ----------------
__global__ void finalize2_kernel(float* __restrict__ out,
                                 const float* __restrict__ b2, int n) {
    int i = blockIdx.x * blockDim.x + threadIdx.x;
    int total = n * OUTF;
    if (i >= total) return;
    int r = i >> 4;
    int c = i & 15;
    out[i] = out[i] * g_norm_dst[r] + __ldg(&b2[c]);
}

extern "C" void kernel_launch(void* const* d_in, const int* in_sizes, int n_in,
                              void* d_out, int out_size) {
    const float* features = (const float*)d_in[0];
    const int*   src      = (const int*)d_in[1];
    const int*   dst      = (const int*)d_in[2];
    const float* W1       = (const float*)d_in[3];
    const float* b1       = (const float*)d_in[4];
    const float* W2       = (const float*)d_in[5];
    const float* b2       = (const float*)d_in[6];
    float* out = (float*)d_out;

    int n = in_sizes[0] / FEAT;   // 50000
    int e = in_sizes[1];          // 800000

    const int T = 256;

    // degrees / norms
    zero_deg_kernel<<<(n + T - 1) / T, T>>>(n);
    count_deg_kernel<<<(e + T - 1) / T, T>>>(src, dst, e);
    norm_kernel<<<(n + T - 1) / T, T>>>(n);

    // layer 1
    gemm1_kernel<<<(n + 7) / 8, T>>>(features, W1, n);

    float* agg1;
    cudaGetSymbolAddress((void**)&agg1, g_agg1);
    zero_f_kernel<<<(n * FEAT + T - 1) / T, T>>>(agg1, n * FEAT);

    scatter64_kernel<<<(e * FEAT + T - 1) / T, T>>>(src, dst, e);
    finalize1_kernel<<<(n * FEAT + T - 1) / T, T>>>(b1, n);

    // layer 2
    gemm2_kernel<<<(n + 15) / 16, T>>>(W2, n);
    zero_f_kernel<<<(n * OUTF + T - 1) / T, T>>>(out, n * OUTF);
    scatter16_kernel<<<(e * OUTF + T - 1) / T, T>>>(src, dst, out, e);
    finalize2_kernel<<<(n * OUTF + T - 1) / T, T>>>(out, b2, n);
}

// round 2
// speedup vs baseline: 2.2832x; 2.2832x over previous
#include <cuda_runtime.h>

#define NMAX 50000
#define EMAX 800000
#define FEAT 64
#define OUTF 16
#define SCAN_BS 256

// Scratch (no allocations allowed)
__device__ float g_h1[NMAX * FEAT];     // (X@W1) * norm_src
__device__ float g_out1[NMAX * FEAT];   // relu(agg * norm_dst + b1)
__device__ float g_h2[NMAX * OUTF];     // (out1@W2) * norm_src
__device__ float g_norm_src[NMAX];
__device__ float g_norm_dst[NMAX];
__device__ int   g_deg_src[NMAX];
__device__ int   g_deg_dst[NMAX];
__device__ int   g_cnt[NMAX];
__device__ int   g_scan[NMAX];          // intra-block exclusive scan of deg_dst
__device__ int   g_bsum[SCAN_BS];       // per-block sums (NB <= 256)
__device__ int   g_off[NMAX + 1];       // CSR offsets by dst
__device__ int   g_csr_src[EMAX];       // src ids grouped by dst

// ---------------- zero ----------------
__global__ void zero_kernel(int n) {
    int i = blockIdx.x * blockDim.x + threadIdx.x;
    if (i < n) { g_deg_src[i] = 0; g_deg_dst[i] = 0; g_cnt[i] = 0; }
}

// ---------------- degree count ----------------
__global__ void count_deg_kernel(const int* __restrict__ src,
                                 const int* __restrict__ dst, int e) {
    int i = blockIdx.x * blockDim.x + threadIdx.x;
    if (i < e) {
        atomicAdd(&g_deg_src[src[i]], 1);
        atomicAdd(&g_deg_dst[dst[i]], 1);
    }
}

// ---------------- norms ----------------
__global__ void norm_kernel(int n) {
    int i = blockIdx.x * blockDim.x + threadIdx.x;
    if (i < n) {
        g_norm_src[i] = rsqrtf(fmaxf((float)g_deg_src[i], 1.0f));
        g_norm_dst[i] = rsqrtf(fmaxf((float)g_deg_dst[i], 1.0f));
    }
}

// ---------------- scan phase A: per-block exclusive scan of deg_dst ----------------
__global__ void scanA_kernel(int n) {
    __shared__ int sh[SCAN_BS];
    int t = threadIdx.x;
    int i = blockIdx.x * SCAN_BS + t;
    int v = (i < n) ? g_deg_dst[i] : 0;
    sh[t] = v;
    __syncthreads();
#pragma unroll
    for (int d = 1; d < SCAN_BS; d <<= 1) {
        int tv = (t >= d) ? sh[t - d] : 0;
        __syncthreads();
        sh[t] += tv;
        __syncthreads();
    }
    if (i < n) g_scan[i] = sh[t] - v;           // exclusive within block
    if (t == SCAN_BS - 1) g_bsum[blockIdx.x] = sh[t];
}

// ---------------- scan phase B: exclusive scan of block sums (single block) ----------------
__global__ void scanB_kernel(int nb) {
    __shared__ int sh[SCAN_BS];
    int t = threadIdx.x;
    int v = (t < nb) ? g_bsum[t] : 0;
    sh[t] = v;
    __syncthreads();
#pragma unroll
    for (int d = 1; d < SCAN_BS; d <<= 1) {
        int tv = (t >= d) ? sh[t - d] : 0;
        __syncthreads();
        sh[t] += tv;
        __syncthreads();
    }
    if (t < nb) g_bsum[t] = sh[t] - v;          // exclusive
}

// ---------------- scan phase C: combine -> g_off ----------------
__global__ void scanC_kernel(int n, int e) {
    int i = blockIdx.x * blockDim.x + threadIdx.x;
    if (i < n) {
        g_off[i] = g_scan[i] + g_bsum[i / SCAN_BS];
        if (i == n - 1) g_off[n] = e;
    }
}

// ---------------- CSR fill ----------------
__global__ void fill_kernel(const int* __restrict__ src,
                            const int* __restrict__ dst, int e) {
    int i = blockIdx.x * blockDim.x + threadIdx.x;
    if (i < e) {
        int d = dst[i];
        int pos = g_off[d] + atomicAdd(&g_cnt[d], 1);
        g_csr_src[pos] = src[i];
    }
}

// ---------------- GEMM 1: h1 = (X @ W1) * norm_src ----------------
// Warp handles 4 rows; x in registers (float2/lane), distributed via shfl;
// W row read once per k as one LDS.64 serving 8 FMAs.
__global__ void gemm1_kernel(const float* __restrict__ x,
                             const float* __restrict__ w1, int n) {
    __shared__ float ws[FEAT * FEAT];
    int tid = threadIdx.x;
    for (int i = tid; i < FEAT * FEAT; i += blockDim.x) ws[i] = w1[i];
    __syncthreads();

    int warp = tid >> 5;
    int lane = tid & 31;
    int r0 = (blockIdx.x * 8 + warp) * 4;
    if (r0 >= n) return;
    int rmax = n - r0;

    float2 xq[4];
#pragma unroll
    for (int j = 0; j < 4; j++) {
        xq[j] = (j < rmax) ? __ldg((const float2*)(x + (r0 + j) * FEAT) + lane)
                           : make_float2(0.f, 0.f);
    }

    float2 acc[4];
#pragma unroll
    for (int j = 0; j < 4; j++) acc[j] = make_float2(0.f, 0.f);

    const float2* ws2 = (const float2*)ws;
#pragma unroll
    for (int k = 0; k < FEAT; k++) {
        float2 wv = ws2[k * 32 + lane];    // cols (2*lane, 2*lane+1) of W row k
#pragma unroll
        for (int j = 0; j < 4; j++) {
            float xv = __shfl_sync(0xffffffffu, (k & 1) ? xq[j].y : xq[j].x, k >> 1);
            acc[j].x = fmaf(xv, wv.x, acc[j].x);
            acc[j].y = fmaf(xv, wv.y, acc[j].y);
        }
    }

#pragma unroll
    for (int j = 0; j < 4; j++) {
        int r = r0 + j;
        if (r < n) {
            float s = g_norm_src[r];
            ((float2*)g_h1)[r * 32 + lane] = make_float2(acc[j].x * s, acc[j].y * s);
        }
    }
}

// ---------------- Gather layer 1 (fused finalize + relu) ----------------
// Warp per dst node; lane owns feats (2*lane, 2*lane+1).
__global__ void gather1_kernel(const float* __restrict__ b1, int n) {
    int warp = threadIdx.x >> 5;
    int lane = threadIdx.x & 31;
    int node = blockIdx.x * 8 + warp;
    if (node >= n) return;

    int beg = g_off[node];
    int end = g_off[node + 1];
    const float2* h1v = (const float2*)g_h1;

    float2 acc = make_float2(0.f, 0.f);
    int j = beg;
    for (; j + 4 <= end; j += 4) {
        int s0 = __ldg(&g_csr_src[j]);
        int s1 = __ldg(&g_csr_src[j + 1]);
        int s2 = __ldg(&g_csr_src[j + 2]);
        int s3 = __ldg(&g_csr_src[j + 3]);
        float2 v0 = __ldg(h1v + s0 * 32 + lane);
        float2 v1 = __ldg(h1v + s1 * 32 + lane);
        float2 v2 = __ldg(h1v + s2 * 32 + lane);
        float2 v3 = __ldg(h1v + s3 * 32 + lane);
        acc.x += (v0.x + v1.x) + (v2.x + v3.x);
        acc.y += (v0.y + v1.y) + (v2.y + v3.y);
    }
    for (; j < end; j++) {
        int s = __ldg(&g_csr_src[j]);
        float2 v = __ldg(h1v + s * 32 + lane);
        acc.x += v.x;
        acc.y += v.y;
    }

    float nd = g_norm_dst[node];
    float2 bb = __ldg((const float2*)b1 + lane);
    float2 o;
    o.x = fmaxf(fmaf(acc.x, nd, bb.x), 0.f);
    o.y = fmaxf(fmaf(acc.y, nd, bb.y), 0.f);
    ((float2*)g_out1)[node * 32 + lane] = o;
}

// ---------------- GEMM 2: h2 = (out1 @ W2) * norm_src ----------------
// Warp handles 4 rows; lane group g = lane>>4 covers rows (r0+g, r0+g+2), col = lane&15.
__global__ void gemm2_kernel(const float* __restrict__ w2, int n) {
    __shared__ float ws[FEAT * OUTF];
    int tid = threadIdx.x;
    for (int i = tid; i < FEAT * OUTF; i += blockDim.x) ws[i] = w2[i];
    __syncthreads();

    int warp = tid >> 5;
    int lane = tid & 31;
    int r0 = (blockIdx.x * 8 + warp) * 4;
    if (r0 >= n) return;
    int rmax = n - r0;

    float2 xq[4];
#pragma unroll
    for (int j = 0; j < 4; j++) {
        xq[j] = (j < rmax) ? ((const float2*)g_out1)[(r0 + j) * 32 + lane]
                           : make_float2(0.f, 0.f);
    }

    int g = lane >> 4;
    int c = lane & 15;
    float accA = 0.f, accB = 0.f;     // rows r0+g and r0+g+2

#pragma unroll
    for (int k = 0; k < FEAT; k++) {
        float wv = ws[k * OUTF + c];
        float x0 = __shfl_sync(0xffffffffu, (k & 1) ? xq[0].y : xq[0].x, k >> 1);
        float x1 = __shfl_sync(0xffffffffu, (k & 1) ? xq[1].y : xq[1].x, k >> 1);
        float x2 = __shfl_sync(0xffffffffu, (k & 1) ? xq[2].y : xq[2].x, k >> 1);
        float x3 = __shfl_sync(0xffffffffu, (k & 1) ? xq[3].y : xq[3].x, k >> 1);
        float xA = g ? x1 : x0;
        float xB = g ? x3 : x2;
        accA = fmaf(xA, wv, accA);
        accB = fmaf(xB, wv, accB);
    }

    int rA = r0 + g;
    int rB = r0 + g + 2;
    if (rA < n) g_h2[rA * OUTF + c] = accA * g_norm_src[rA];
    if (rB < n) g_h2[rB * OUTF + c] = accB * g_norm_src[rB];
}

// ---------------- Gather layer 2 (fused finalize) ----------------
// Warp per dst node; lanes 0-15 take even edges, 16-31 odd; combine via shfl_xor.
__global__ void gather2_kernel(float* __restrict__ out,
                               const float* __restrict__ b2, int n) {
    int warp = threadIdx.x >> 5;
    int lane = threadIdx.x & 31;
    int node = blockIdx.x * 8 + warp;
    if (node >= n) return;

    int beg = g_off[node];
    int end = g_off[node + 1];
    int f = lane & 15;
    int par = lane >> 4;

    float acc = 0.f;
    int j = beg + par;
    for (; j + 2 < end; j += 4) {
        int s0 = __ldg(&g_csr_src[j]);
        int s1 = __ldg(&g_csr_src[j + 2]);
        acc += __ldg(&g_h2[s0 * OUTF + f]);
        acc += __ldg(&g_h2[s1 * OUTF + f]);
    }
    for (; j < end; j += 2) {
        int s = __ldg(&g_csr_src[j]);
        acc += __ldg(&g_h2[s * OUTF + f]);
    }

    acc += __shfl_xor_sync(0xffffffffu, acc, 16);
    if (lane < 16) {
        out[node * OUTF + f] = fmaf(acc, g_norm_dst[node], __ldg(&b2[f]));
    }
}

extern "C" void kernel_launch(void* const* d_in, const int* in_sizes, int n_in,
                              void* d_out, int out_size) {
    const float* features = (const float*)d_in[0];
    const int*   src      = (const int*)d_in[1];
    const int*   dst      = (const int*)d_in[2];
    const float* W1       = (const float*)d_in[3];
    const float* b1       = (const float*)d_in[4];
    const float* W2       = (const float*)d_in[5];
    const float* b2       = (const float*)d_in[6];
    float* out = (float*)d_out;

    int n = in_sizes[0] / FEAT;   // 50000
    int e = in_sizes[1];          // 800000

    const int T = 256;
    int nb = (n + SCAN_BS - 1) / SCAN_BS;   // 196 (<= 256)

    // degrees / norms / CSR
    zero_kernel<<<(n + T - 1) / T, T>>>(n);
    count_deg_kernel<<<(e + T - 1) / T, T>>>(src, dst, e);
    norm_kernel<<<(n + T - 1) / T, T>>>(n);
    scanA_kernel<<<nb, SCAN_BS>>>(n);
    scanB_kernel<<<1, SCAN_BS>>>(nb);
    scanC_kernel<<<(n + T - 1) / T, T>>>(n, e);
    fill_kernel<<<(e + T - 1) / T, T>>>(src, dst, e);

    // layer 1
    gemm1_kernel<<<(n + 31) / 32, T>>>(features, W1, n);
    gather1_kernel<<<(n + 7) / 8, T>>>(b1, n);

    // layer 2
    gemm2_kernel<<<(n + 31) / 32, T>>>(W2, n);
    gather2_kernel<<<(n + 7) / 8, T>>>(out, b2, n);
}

// round 4
// speedup vs baseline: 2.3170x; 1.0148x over previous
#include <cuda_runtime.h>
#include <cuda_fp16.h>

#define NMAX 50000
#define EMAX 800000
#define FEAT 64
#define OUTF 16
#define SCAN_BS 256

// Scratch (no allocations allowed)
__device__ __half g_h1[NMAX * FEAT];    // (X@W1) * norm_src, fp16
__device__ float  g_out1[NMAX * FEAT];  // relu(agg * norm_dst + b1), fp32
__device__ __half g_h2[NMAX * OUTF];    // (out1@W2) * norm_src, fp16
__device__ float  g_norm_src[NMAX];
__device__ float  g_norm_dst[NMAX];
__device__ int    g_deg_src[NMAX];
__device__ int    g_deg_dst[NMAX];
__device__ int    g_cnt[NMAX];
__device__ int    g_scan[NMAX];         // intra-block exclusive scan of deg_dst
__device__ int    g_bsum[SCAN_BS];      // per-block sums (nb <= 256), excl-scanned in place
__device__ int    g_csr_src[EMAX];      // src ids grouped by dst

// ---------------- zero ----------------
__global__ void zero_kernel(int n) {
    int i = blockIdx.x * blockDim.x + threadIdx.x;
    if (i < n) { g_deg_src[i] = 0; g_deg_dst[i] = 0; g_cnt[i] = 0; }
}

// ---------------- degree count ----------------
__global__ void count_deg_kernel(const int* __restrict__ src,
                                 const int* __restrict__ dst, int e) {
    int i = blockIdx.x * blockDim.x + threadIdx.x;
    if (i < e) {
        atomicAdd(&g_deg_src[src[i]], 1);
        atomicAdd(&g_deg_dst[dst[i]], 1);
    }
}

// ---------------- scan A: per-block exclusive scan of deg_dst + norms ----------------
__global__ void scanA_kernel(int n) {
    int t = threadIdx.x;
    int i = blockIdx.x * SCAN_BS + t;
    int v = (i < n) ? g_deg_dst[i] : 0;
    if (i < n) {
        g_norm_src[i] = rsqrtf(fmaxf((float)g_deg_src[i], 1.0f));
        g_norm_dst[i] = rsqrtf(fmaxf((float)v, 1.0f));
    }
    int lane = t & 31, w = t >> 5;
    int incl = v;
#pragma unroll
    for (int d = 1; d < 32; d <<= 1) {
        int x = __shfl_up_sync(0xffffffffu, incl, d);
        if (lane >= d) incl += x;
    }
    __shared__ int wsum[8];
    if (lane == 31) wsum[w] = incl;
    __syncthreads();
    if (w == 0) {
        int s = (lane < 8) ? wsum[lane] : 0;
#pragma unroll
        for (int d = 1; d < 8; d <<= 1) {
            int x = __shfl_up_sync(0xffffffffu, s, d);
            if (lane >= d) s += x;
        }
        if (lane < 8) wsum[lane] = s;
    }
    __syncthreads();
    int excl = incl - v + (w > 0 ? wsum[w - 1] : 0);
    if (i < n) g_scan[i] = excl;
    if (t == SCAN_BS - 1) g_bsum[blockIdx.x] = excl + v;   // block total
}

// ---------------- scan B: exclusive scan of block sums (single block) ----------------
__global__ void scanB_kernel(int nb) {
    int t = threadIdx.x;
    int v = (t < nb) ? g_bsum[t] : 0;
    int lane = t & 31, w = t >> 5;
    int incl = v;
#pragma unroll
    for (int d = 1; d < 32; d <<= 1) {
        int x = __shfl_up_sync(0xffffffffu, incl, d);
        if (lane >= d) incl += x;
    }
    __shared__ int wsum[8];
    if (lane == 31) wsum[w] = incl;
    __syncthreads();
    if (w == 0) {
        int s = (lane < 8) ? wsum[lane] : 0;
#pragma unroll
        for (int d = 1; d < 8; d <<= 1) {
            int x = __shfl_up_sync(0xffffffffu, s, d);
            if (lane >= d) s += x;
        }
        if (lane < 8) wsum[lane] = s;
    }
    __syncthreads();
    int excl = incl - v + (w > 0 ? wsum[w - 1] : 0);
    if (t < nb) g_bsum[t] = excl;
}

// ---------------- CSR fill (offset computed inline) ----------------
__global__ void fill_kernel(const int* __restrict__ src,
                            const int* __restrict__ dst, int e) {
    int i = blockIdx.x * blockDim.x + threadIdx.x;
    if (i < e) {
        int d = dst[i];
        int base = g_scan[d] + g_bsum[d >> 8];
        int pos = base + atomicAdd(&g_cnt[d], 1);
        g_csr_src[pos] = src[i];
    }
}

// ---------------- GEMM 1: h1 = (X @ W1) * norm_src -> fp16 ----------------
__global__ void gemm1_kernel(const float* __restrict__ x,
                             const float* __restrict__ w1, int n) {
    __shared__ float ws[FEAT * FEAT];
    int tid = threadIdx.x;
    for (int i = tid; i < FEAT * FEAT; i += blockDim.x) ws[i] = w1[i];
    __syncthreads();

    int warp = tid >> 5;
    int lane = tid & 31;
    int r0 = (blockIdx.x * 8 + warp) * 4;
    if (r0 >= n) return;
    int rmax = n - r0;

    float2 xq[4];
#pragma unroll
    for (int j = 0; j < 4; j++) {
        xq[j] = (j < rmax) ? __ldg((const float2*)(x + (r0 + j) * FEAT) + lane)
                           : make_float2(0.f, 0.f);
    }

    float2 acc[4];
#pragma unroll
    for (int j = 0; j < 4; j++) acc[j] = make_float2(0.f, 0.f);

    const float2* ws2 = (const float2*)ws;
#pragma unroll
    for (int k = 0; k < FEAT; k++) {
        float2 wv = ws2[k * 32 + lane];
#pragma unroll
        for (int j = 0; j < 4; j++) {
            float xv = __shfl_sync(0xffffffffu, (k & 1) ? xq[j].y : xq[j].x, k >> 1);
            acc[j].x = fmaf(xv, wv.x, acc[j].x);
            acc[j].y = fmaf(xv, wv.y, acc[j].y);
        }
    }

#pragma unroll
    for (int j = 0; j < 4; j++) {
        int r = r0 + j;
        if (r < n) {
            float s = g_norm_src[r];
            ((half2*)g_h1)[r * 32 + lane] =
                __float22half2_rn(make_float2(acc[j].x * s, acc[j].y * s));
        }
    }
}

// ---------------- Gather layer 1 (fused finalize + relu) ----------------
// Warp per dst node; lane owns feats (2*lane, 2*lane+1) as one half2 (4B/lane, 128B/row).
__global__ void gather1_kernel(const float* __restrict__ b1, int n) {
    int warp = threadIdx.x >> 5;
    int lane = threadIdx.x & 31;
    int node = blockIdx.x * 8 + warp;
    if (node >= n) return;

    int beg = g_scan[node] + g_bsum[node >> 8];
    int end = beg + g_deg_dst[node];
    const half2* h1v = (const half2*)g_h1;

    float2 acc = make_float2(0.f, 0.f);
    int j = beg;
    for (; j + 4 <= end; j += 4) {
        int s0 = __ldg(&g_csr_src[j]);
        int s1 = __ldg(&g_csr_src[j + 1]);
        int s2 = __ldg(&g_csr_src[j + 2]);
        int s3 = __ldg(&g_csr_src[j + 3]);
        float2 v0 = __half22float2(__ldg(h1v + s0 * 32 + lane));
        float2 v1 = __half22float2(__ldg(h1v + s1 * 32 + lane));
        float2 v2 = __half22float2(__ldg(h1v + s2 * 32 + lane));
        float2 v3 = __half22float2(__ldg(h1v + s3 * 32 + lane));
        acc.x += (v0.x + v1.x) + (v2.x + v3.x);
        acc.y += (v0.y + v1.y) + (v2.y + v3.y);
    }
    for (; j < end; j++) {
        int s = __ldg(&g_csr_src[j]);
        float2 v = __half22float2(__ldg(h1v + s * 32 + lane));
        acc.x += v.x;
        acc.y += v.y;
    }

    float nd = g_norm_dst[node];
    float2 bb = __ldg((const float2*)b1 + lane);
    float2 o;
    o.x = fmaxf(fmaf(acc.x, nd, bb.x), 0.f);
    o.y = fmaxf(fmaf(acc.y, nd, bb.y), 0.f);
    ((float2*)g_out1)[node * 32 + lane] = o;
}

// ---------------- GEMM 2: h2 = (out1 @ W2) * norm_src -> fp16 ----------------
__global__ void gemm2_kernel(const float* __restrict__ w2, int n) {
    __shared__ float ws[FEAT * OUTF];
    int tid = threadIdx.x;
    for (int i = tid; i < FEAT * OUTF; i += blockDim.x) ws[i] = w2[i];
    __syncthreads();

    int warp = tid >> 5;
    int lane = tid & 31;
    int r0 = (blockIdx.x * 8 + warp) * 4;
    if (r0 >= n) return;
    int rmax = n - r0;

    float2 xq[4];
#pragma unroll
    for (int j = 0; j < 4; j++) {
        xq[j] = (j < rmax) ? ((const float2*)g_out1)[(r0 + j) * 32 + lane]
                           : make_float2(0.f, 0.f);
    }

    int g = lane >> 4;
    int c = lane & 15;
    float accA = 0.f, accB = 0.f;

#pragma unroll
    for (int k = 0; k < FEAT; k++) {
        float wv = ws[k * OUTF + c];
        float x0 = __shfl_sync(0xffffffffu, (k & 1) ? xq[0].y : xq[0].x, k >> 1);
        float x1 = __shfl_sync(0xffffffffu, (k & 1) ? xq[1].y : xq[1].x, k >> 1);
        float x2 = __shfl_sync(0xffffffffu, (k & 1) ? xq[2].y : xq[2].x, k >> 1);
        float x3 = __shfl_sync(0xffffffffu, (k & 1) ? xq[3].y : xq[3].x, k >> 1);
        float xA = g ? x1 : x0;
        float xB = g ? x3 : x2;
        accA = fmaf(xA, wv, accA);
        accB = fmaf(xB, wv, accB);
    }

    int rA = r0 + g;
    int rB = r0 + g + 2;
    if (rA < n) g_h2[rA * OUTF + c] = __float2half(accA * g_norm_src[rA]);
    if (rB < n) g_h2[rB * OUTF + c] = __float2half(accB * g_norm_src[rB]);
}

// ---------------- Gather layer 2 (fused finalize) ----------------
__global__ void gather2_kernel(float* __restrict__ out,
                               const float* __restrict__ b2, int n) {
    int warp = threadIdx.x >> 5;
    int lane = threadIdx.x & 31;
    int node = blockIdx.x * 8 + warp;
    if (node >= n) return;

    int beg = g_scan[node] + g_bsum[node >> 8];
    int end = beg + g_deg_dst[node];
    int f = lane & 15;
    int par = lane >> 4;

    float acc = 0.f;
    int j = beg + par;
    for (; j + 2 < end; j += 4) {
        int s0 = __ldg(&g_csr_src[j]);
        int s1 = __ldg(&g_csr_src[j + 2]);
        acc += __half2float(__ldg(&g_h2[s0 * OUTF + f]));
        acc += __half2float(__ldg(&g_h2[s1 * OUTF + f]));
    }
    for (; j < end; j += 2) {
        int s = __ldg(&g_csr_src[j]);
        acc += __half2float(__ldg(&g_h2[s * OUTF + f]));
    }

    acc += __shfl_xor_sync(0xffffffffu, acc, 16);
    if (lane < 16) {
        out[node * OUTF + f] = fmaf(acc, g_norm_dst[node], __ldg(&b2[f]));
    }
}

extern "C" void kernel_launch(void* const* d_in, const int* in_sizes, int n_in,
                              void* d_out, int out_size) {
    const float* features = (const float*)d_in[0];
    const int*   src      = (const int*)d_in[1];
    const int*   dst      = (const int*)d_in[2];
    const float* W1       = (const float*)d_in[3];
    const float* b1       = (const float*)d_in[4];
    const float* W2       = (const float*)d_in[5];
    const float* b2       = (const float*)d_in[6];
    float* out = (float*)d_out;

    int n = in_sizes[0] / FEAT;   // 50000
    int e = in_sizes[1];          // 800000

    const int T = 256;
    int nb = (n + SCAN_BS - 1) / SCAN_BS;   // 196 (<= 256)

    // degrees / norms / CSR
    zero_kernel<<<(n + T - 1) / T, T>>>(n);
    count_deg_kernel<<<(e + T - 1) / T, T>>>(src, dst, e);
    scanA_kernel<<<nb, SCAN_BS>>>(n);
    scanB_kernel<<<1, SCAN_BS>>>(nb);
    fill_kernel<<<(e + T - 1) / T, T>>>(src, dst, e);

    // layer 1
    gemm1_kernel<<<(n + 31) / 32, T>>>(features, W1, n);
    gather1_kernel<<<(n + 7) / 8, T>>>(b1, n);

    // layer 2
    gemm2_kernel<<<(n + 31) / 32, T>>>(W2, n);
    gather2_kernel<<<(n + 7) / 8, T>>>(out, b2, n);
}

// round 5
// speedup vs baseline: 2.4413x; 1.0536x over previous
#include <cuda_runtime.h>
#include <cuda_fp16.h>

#define NMAX 50000
#define EMAX 800000
#define FEAT 64
#define OUTF 16
#define SCAN_BS 256

// Scratch (no allocations allowed). All zero-initialized at module load;
// gather2 re-zeroes the counters it consumed so every replay starts clean.
__device__ __half g_h1[NMAX * FEAT];    // (X@W1) * norm_src, fp16
__device__ __half g_h2[NMAX * OUTF];    // (out1@W2) * norm_src, fp16
__device__ float  g_norm_src[NMAX];
__device__ float  g_norm_dst[NMAX];
__device__ int    g_deg_src[NMAX];
__device__ int    g_deg_dst[NMAX];
__device__ int    g_cnt[NMAX];
__device__ int    g_scan[NMAX];         // intra-block exclusive scan of deg_dst
__device__ int    g_bsum[SCAN_BS];      // raw per-block sums
__device__ int    g_bsum_s[SCAN_BS];    // exclusive-scanned block sums
__device__ int    g_done;               // scanA completion ticket
__device__ int    g_csr_src[EMAX];      // src ids grouped by dst

// ---------------- degree count ----------------
__global__ void count_deg_kernel(const int* __restrict__ src,
                                 const int* __restrict__ dst, int e) {
    int i = blockIdx.x * blockDim.x + threadIdx.x;
    if (i < e) {
        atomicAdd(&g_deg_src[src[i]], 1);
        atomicAdd(&g_deg_dst[dst[i]], 1);
    }
}

// ---------------- scan A: norms + block scan of deg_dst; last block scans bsum ----------------
__global__ void scanA_kernel(int n) {
    int t = threadIdx.x;
    int i = blockIdx.x * SCAN_BS + t;
    int v = (i < n) ? g_deg_dst[i] : 0;
    if (i < n) {
        g_norm_src[i] = rsqrtf(fmaxf((float)g_deg_src[i], 1.0f));
        g_norm_dst[i] = rsqrtf(fmaxf((float)v, 1.0f));
    }
    int lane = t & 31, w = t >> 5;
    int incl = v;
#pragma unroll
    for (int d = 1; d < 32; d <<= 1) {
        int x = __shfl_up_sync(0xffffffffu, incl, d);
        if (lane >= d) incl += x;
    }
    __shared__ int wsum[8];
    if (lane == 31) wsum[w] = incl;
    __syncthreads();
    if (w == 0) {
        int s = (lane < 8) ? wsum[lane] : 0;
#pragma unroll
        for (int d = 1; d < 8; d <<= 1) {
            int x = __shfl_up_sync(0xffffffffu, s, d);
            if (lane >= d) s += x;
        }
        if (lane < 8) wsum[lane] = s;
    }
    __syncthreads();
    int excl = incl - v + (w > 0 ? wsum[w - 1] : 0);
    if (i < n) g_scan[i] = excl;
    if (t == SCAN_BS - 1) g_bsum[blockIdx.x] = excl + v;   // block total

    // last-finishing block scans g_bsum -> g_bsum_s (replaces scanB kernel)
    __threadfence();
    __syncthreads();
    __shared__ int amLast;
    if (t == 0) amLast = (atomicAdd(&g_done, 1) == (int)gridDim.x - 1);
    __syncthreads();
    if (amLast) {
        int nb = gridDim.x;
        if (t < 32) {
            int carry = 0;
            for (int base = 0; base < nb; base += 32) {
                int idx = base + t;
                int bv = (idx < nb) ? g_bsum[idx] : 0;
                int bi = bv;
#pragma unroll
                for (int d = 1; d < 32; d <<= 1) {
                    int x = __shfl_up_sync(0xffffffffu, bi, d);
                    if (t >= d) bi += x;
                }
                if (idx < nb) g_bsum_s[idx] = carry + bi - bv;
                carry += __shfl_sync(0xffffffffu, bi, 31);
            }
            if (t == 0) g_done = 0;   // reset ticket for next replay
        }
    }
}

// ---------------- CSR fill ----------------
__global__ void fill_kernel(const int* __restrict__ src,
                            const int* __restrict__ dst, int e) {
    int i = blockIdx.x * blockDim.x + threadIdx.x;
    if (i < e) {
        int d = dst[i];
        int base = g_scan[d] + g_bsum_s[d >> 8];
        int pos = base + atomicAdd(&g_cnt[d], 1);
        g_csr_src[pos] = src[i];
    }
}

// ---------------- GEMM 1: h1 = (X @ W1) * norm_src -> fp16 ----------------
__global__ void gemm1_kernel(const float* __restrict__ x,
                             const float* __restrict__ w1, int n) {
    __shared__ float ws[FEAT * FEAT];
    int tid = threadIdx.x;
    for (int i = tid; i < FEAT * FEAT; i += blockDim.x) ws[i] = w1[i];
    __syncthreads();

    int warp = tid >> 5;
    int lane = tid & 31;
    int r0 = (blockIdx.x * 8 + warp) * 4;
    if (r0 >= n) return;
    int rmax = n - r0;

    float2 xq[4];
#pragma unroll
    for (int j = 0; j < 4; j++) {
        xq[j] = (j < rmax) ? __ldg((const float2*)(x + (r0 + j) * FEAT) + lane)
                           : make_float2(0.f, 0.f);
    }

    float2 acc[4];
#pragma unroll
    for (int j = 0; j < 4; j++) acc[j] = make_float2(0.f, 0.f);

    const float2* ws2 = (const float2*)ws;
#pragma unroll
    for (int k = 0; k < FEAT; k++) {
        float2 wv = ws2[k * 32 + lane];
#pragma unroll
        for (int j = 0; j < 4; j++) {
            float xv = __shfl_sync(0xffffffffu, (k & 1) ? xq[j].y : xq[j].x, k >> 1);
            acc[j].x = fmaf(xv, wv.x, acc[j].x);
            acc[j].y = fmaf(xv, wv.y, acc[j].y);
        }
    }

#pragma unroll
    for (int j = 0; j < 4; j++) {
        int r = r0 + j;
        if (r < n) {
            float s = g_norm_src[r];
            ((half2*)g_h1)[r * 32 + lane] =
                __float22half2_rn(make_float2(acc[j].x * s, acc[j].y * s));
        }
    }
}

// ---------------- Gather 1 + finalize + relu + FUSED GEMM2 ----------------
// Warp per dst node. Aggregates h1[src] rows, applies norm/bias/relu in
// registers (the out1 row never touches memory), then computes the 16-wide
// h2 row = (out1 @ W2) * norm_src via shuffles and stores fp16.
__global__ void gather1_kernel(const float* __restrict__ b1,
                               const float* __restrict__ w2, int n) {
    __shared__ float ws[FEAT * OUTF];
    int tid = threadIdx.x;
    for (int i = tid; i < FEAT * OUTF; i += blockDim.x) ws[i] = w2[i];
    __syncthreads();

    int warp = tid >> 5;
    int lane = tid & 31;
    int node = blockIdx.x * 8 + warp;
    if (node >= n) return;

    int beg = g_scan[node] + g_bsum_s[node >> 8];
    int end = beg + g_deg_dst[node];
    const half2* h1v = (const half2*)g_h1;

    float2 acc = make_float2(0.f, 0.f);
    int j = beg;
    for (; j + 4 <= end; j += 4) {
        int s0 = __ldg(&g_csr_src[j]);
        int s1 = __ldg(&g_csr_src[j + 1]);
        int s2 = __ldg(&g_csr_src[j + 2]);
        int s3 = __ldg(&g_csr_src[j + 3]);
        float2 v0 = __half22float2(__ldg(h1v + s0 * 32 + lane));
        float2 v1 = __half22float2(__ldg(h1v + s1 * 32 + lane));
        float2 v2 = __half22float2(__ldg(h1v + s2 * 32 + lane));
        float2 v3 = __half22float2(__ldg(h1v + s3 * 32 + lane));
        acc.x += (v0.x + v1.x) + (v2.x + v3.x);
        acc.y += (v0.y + v1.y) + (v2.y + v3.y);
    }
    for (; j < end; j++) {
        int s = __ldg(&g_csr_src[j]);
        float2 v = __half22float2(__ldg(h1v + s * 32 + lane));
        acc.x += v.x;
        acc.y += v.y;
    }

    float nd = g_norm_dst[node];
    float2 bb = __ldg((const float2*)b1 + lane);
    float2 o;                                    // out1 row, 2 feats per lane
    o.x = fmaxf(fmaf(acc.x, nd, bb.x), 0.f);
    o.y = fmaxf(fmaf(acc.y, nd, bb.y), 0.f);

    // fused GEMM2: lanes 0-15 cover k=0..31, lanes 16-31 cover k=32..63
    int c = lane & 15;
    int hf = lane >> 4;
    float a2 = 0.f;
#pragma unroll
    for (int kk = 0; kk < 32; kk++) {
        int k = hf * 32 + kk;
        float xv = __shfl_sync(0xffffffffu, (k & 1) ? o.y : o.x, k >> 1);
        a2 = fmaf(xv, ws[k * OUTF + c], a2);
    }
    a2 += __shfl_xor_sync(0xffffffffu, a2, 16);
    if (lane < 16) {
        g_h2[node * OUTF + lane] = __float2half(a2 * g_norm_src[node]);
    }
}

// ---------------- Gather 2 + finalize -> out; also resets counters ----------------
__global__ void gather2_kernel(float* __restrict__ out,
                               const float* __restrict__ b2, int n) {
    int warp = threadIdx.x >> 5;
    int lane = threadIdx.x & 31;
    int node = blockIdx.x * 8 + warp;
    if (node >= n) return;

    int beg = g_scan[node] + g_bsum_s[node >> 8];
    int deg = g_deg_dst[node];
    int end = beg + deg;
    int f = lane & 15;
    int par = lane >> 4;

    float acc = 0.f;
    int j = beg + par;
    for (; j + 2 < end; j += 4) {
        int s0 = __ldg(&g_csr_src[j]);
        int s1 = __ldg(&g_csr_src[j + 2]);
        acc += __half2float(__ldg(&g_h2[s0 * OUTF + f]));
        acc += __half2float(__ldg(&g_h2[s1 * OUTF + f]));
    }
    for (; j < end; j += 2) {
        int s = __ldg(&g_csr_src[j]);
        acc += __half2float(__ldg(&g_h2[s * OUTF + f]));
    }

    acc += __shfl_xor_sync(0xffffffffu, acc, 16);
    if (lane < 16) {
        out[node * OUTF + f] = fmaf(acc, g_norm_dst[node], __ldg(&b2[f]));
    }

    // reset per-node state for the next replay (zero-init covers the first run)
    if (lane == 0) {
        g_deg_src[node] = 0;
        g_deg_dst[node] = 0;
        g_cnt[node] = 0;
    }
}

extern "C" void kernel_launch(void* const* d_in, const int* in_sizes, int n_in,
                              void* d_out, int out_size) {
    const float* features = (const float*)d_in[0];
    const int*   src      = (const int*)d_in[1];
    const int*   dst      = (const int*)d_in[2];
    const float* W1       = (const float*)d_in[3];
    const float* b1       = (const float*)d_in[4];
    const float* W2       = (const float*)d_in[5];
    const float* b2       = (const float*)d_in[6];
    float* out = (float*)d_out;

    int n = in_sizes[0] / FEAT;   // 50000
    int e = in_sizes[1];          // 800000

    const int T = 256;
    int nb = (n + SCAN_BS - 1) / SCAN_BS;   // 196 (<= 256)

    // side stream + events for overlapping gemm1 with CSR fill
    static cudaStream_t s2 = 0;
    static cudaEvent_t evA = 0, evB = 0;
    if (!s2) {
        cudaStreamCreateWithFlags(&s2, cudaStreamNonBlocking);
        cudaEventCreateWithFlags(&evA, cudaEventDisableTiming);
        cudaEventCreateWithFlags(&evB, cudaEventDisableTiming);
    }

    count_deg_kernel<<<(e + T - 1) / T, T>>>(src, dst, e);
    scanA_kernel<<<nb, SCAN_BS>>>(n);

    // fork: gemm1 depends only on norms (scanA); runs parallel with fill
    cudaEventRecord(evA, 0);
    cudaStreamWaitEvent(s2, evA, 0);
    gemm1_kernel<<<(n + 31) / 32, T, 0, s2>>>(features, W1, n);
    cudaEventRecord(evB, s2);

    fill_kernel<<<(e + T - 1) / T, T>>>(src, dst, e);

    // join: gather1 needs both fill (stream 0) and gemm1 (s2)
    cudaStreamWaitEvent(0, evB, 0);
    gather1_kernel<<<(n + 7) / 8, T>>>(b1, W2, n);
    gather2_kernel<<<(n + 7) / 8, T>>>(out, b2, n);
}